// round 10
// baseline (speedup 1.0000x reference)
#include <cuda_runtime.h>
#include <cuda_fp16.h>
#include <cstdint>

#define NB 4
#define NN 4096
#define LOG2E 1.4426950408889634f

// ---------------- scratch (__device__ globals; no allocation) ----------------
__device__ __align__(256) __half g_Qh[NB * NN * 8];   // [b][n][8], pre-scaled by log2e
__device__ __align__(256) __half g_Kh[NB * NN * 8];   // [b][n][8]
__device__ __align__(256) __half g_Vh[NB * NN * 64];  // [b][n][64]

// ---------------- helpers ----------------
__device__ __forceinline__ uint32_t smem_u32(const void* p) {
    uint32_t a;
    asm("{ .reg .u64 t; cvta.to.shared.u64 t, %1; cvt.u32.u64 %0, t; }" : "=r"(a) : "l"(p));
    return a;
}
__device__ __forceinline__ uint32_t swz128(uint32_t b) { return b ^ ((b >> 3) & 0x70u); }

#define CP_ASYNC16(dst, src) \
    asm volatile("cp.async.cg.shared.global [%0], [%1], 16;" :: "r"(dst), "l"(src) : "memory")
#define CP_COMMIT() asm volatile("cp.async.commit_group;" ::: "memory")
#define CP_WAIT0()  asm volatile("cp.async.wait_group 0;" ::: "memory")
#define PAIR_BAR(kq) asm volatile("bar.sync %0, 64;" :: "r"(1 + (kq)) : "memory")

#define LDSM_X4(r0, r1, r2, r3, a) \
    asm volatile("ldmatrix.sync.aligned.m8n8.x4.shared.b16 {%0,%1,%2,%3}, [%4];" \
                 : "=r"(r0), "=r"(r1), "=r"(r2), "=r"(r3) : "r"(a))
#define LDSM_X4T(r0, r1, r2, r3, a) \
    asm volatile("ldmatrix.sync.aligned.m8n8.x4.trans.shared.b16 {%0,%1,%2,%3}, [%4];" \
                 : "=r"(r0), "=r"(r1), "=r"(r2), "=r"(r3) : "r"(a))

// S(16x8,f16) = Q(16x8,f16) @ K^T ; C = 0
__device__ __forceinline__ void mma16808h(uint32_t* d, uint32_t a0, uint32_t a1, uint32_t b0) {
    uint32_t z = 0;
    asm volatile("mma.sync.aligned.m16n8k8.row.col.f16.f16.f16.f16 "
                 "{%0,%1}, {%2,%3}, {%4}, {%5,%5};"
                 : "=r"(d[0]), "=r"(d[1]) : "r"(a0), "r"(a1), "r"(b0), "r"(z));
}
// O(16x8,f16) += P(16x16,f16) @ V(16x8,f16)
__device__ __forceinline__ void mma16816h(uint32_t* d, const uint32_t* a, uint32_t b0, uint32_t b1) {
    asm volatile("mma.sync.aligned.m16n8k16.row.col.f16.f16.f16.f16 "
                 "{%0,%1}, {%2,%3,%4,%5}, {%6,%7}, {%0,%1};"
                 : "+r"(d[0]), "+r"(d[1])
                 : "r"(a[0]), "r"(a[1]), "r"(a[2]), "r"(a[3]), "r"(b0), "r"(b1));
}
#define EX2H2(r) asm volatile("ex2.approx.f16x2 %0, %0;" : "+r"(r))
__device__ __forceinline__ uint32_t hadd2u(uint32_t a, uint32_t b) {
    uint32_t d; asm("add.rn.f16x2 %0, %1, %2;" : "=r"(d) : "r"(a), "r"(b)); return d;
}
__device__ __forceinline__ float h2sumf(uint32_t r) {
    __half2 h = *reinterpret_cast<__half2*>(&r);
    return __low2float(h) + __high2float(h);
}

// ---------------------------------------------------------------------------
// Kernel 1: fused QKV projections (f16 outputs, staged coalesced stores)
// ---------------------------------------------------------------------------
__global__ __launch_bounds__(256) void prep_kernel(
    const float* __restrict__ x,
    const float* __restrict__ Wq, const float* __restrict__ bq,
    const float* __restrict__ Wk, const float* __restrict__ bk,
    const float* __restrict__ Wv, const float* __restrict__ bv)
{
    __shared__ __align__(16) float xs[64 * 64];
    __shared__ __align__(16) float ws[80 * 64];   // weights; reused as output staging
    __shared__ float bs[80];

    const int t  = threadIdx.x;
    const int b  = blockIdx.y;
    const int n0 = blockIdx.x * 64;

    for (int lin = t; lin < 80 * 64; lin += 256) {
        int o = lin >> 6, c = lin & 63;
        float w;
        if (o < 8)       w = Wq[o * 64 + c] * LOG2E;
        else if (o < 16) w = Wk[(o - 8) * 64 + c];
        else             w = Wv[(o - 16) * 64 + c];
        ws[o * 64 + c] = w;
    }
    if (t < 80) {
        float bb;
        if (t < 8)       bb = bq[t] * LOG2E;
        else if (t < 16) bb = bk[t - 8];
        else             bb = bv[t - 16];
        bs[t] = bb;
    }
    for (int lin = t; lin < 64 * 64; lin += 256) {
        int c = lin >> 6, i = lin & 63;
        xs[c * 64 + i] = x[(b * 64 + c) * NN + n0 + i];
    }
    __syncthreads();

    const int tx = t & 63;
    const int ty = t >> 6;

    float acc[20];
#pragma unroll
    for (int i = 0; i < 20; i++) acc[i] = 0.f;
#pragma unroll
    for (int c = 0; c < 64; c++) {
        float xv = xs[c * 64 + tx];
#pragma unroll
        for (int oo = 0; oo < 20; oo++)
            acc[oo] += ws[(ty * 20 + oo) * 64 + c] * xv;
    }
    float bias[20];
#pragma unroll
    for (int oo = 0; oo < 20; oo++) bias[oo] = bs[ty * 20 + oo];

    __syncthreads();   // done reading ws -> reuse as staging

    // staging: SQ [pix][8ch] (1024B) | SK same (1024B) | SV [pix][64ch], 136B rows
    char* stage = (char*)ws;
#pragma unroll
    for (int oo = 0; oo < 20; oo++) {
        int o = ty * 20 + oo;
        __half h = __float2half(acc[oo] + bias[oo]);
        if (o < 8)
            *(__half*)(stage + tx * 16 + o * 2) = h;
        else if (o < 16)
            *(__half*)(stage + 1024 + tx * 16 + (o - 8) * 2) = h;
        else
            *(__half*)(stage + 2048 + tx * 136 + (o - 16) * 2) = h;
    }
    __syncthreads();

    if (t < 64) {
        *(uint4*)(g_Qh + ((size_t)b * NN + n0 + t) * 8) = *(const uint4*)(stage + t * 16);
    } else if (t < 128) {
        int i = t - 64;
        *(uint4*)(g_Kh + ((size_t)b * NN + n0 + i) * 8) = *(const uint4*)(stage + 1024 + i * 16);
    }
#pragma unroll
    for (int i = 0; i < 4; i++) {
        int lin = t + i * 256;               // 1024 chunks of 8B
        int pix = lin >> 4, chk = lin & 15;
        *(uint2*)(g_Vh + ((size_t)b * NN + n0 + pix) * 64 + chk * 4) =
            *(const uint2*)(stage + 2048 + pix * 136 + chk * 8);
    }
}

// ---------------------------------------------------------------------------
// Kernel 2: flash attention, all-f16 mma.sync, PAIR-DECOUPLED.
// CTA = 64 queries, 8 warps = 4 pairs. Pair kq owns keys [kq*1024, +1024):
// private double-buffered K/V smem, 64-key tiles, 16 iters, 2-warp bar.sync.
// No global barrier in the main loop.
// ---------------------------------------------------------------------------
#define PAIR_STRIDE 18432u      // per pair: K 2x1KB + V 2x8KB
#define SQ_OFF      0u
#define PAIRS_OFF   1024u
#define DSMEM_BYTES (1024u + 4u * PAIR_STRIDE)   // 74752

__global__ __launch_bounds__(256, 2) void attn_kernel(
    const float* __restrict__ x,
    const float* __restrict__ gamma_p,
    float* __restrict__ out)
{
    extern __shared__ __align__(1024) unsigned char dynsm[];

    const int t      = threadIdx.x;
    const int lane   = t & 31;
    const int w      = t >> 5;
    const int rowgrp = w >> 2;          // 0,1 -> rows [32*rowgrp, +32)
    const int kq     = w & 3;           // pair id / key quarter
    const int pt     = rowgrp * 32 + lane;   // 0..63 within pair
    const int b      = blockIdx.y;
    const int q0     = blockIdx.x * 64;

    const uint32_t sb    = smem_u32(dynsm);
    const uint32_t sbQ   = sb + SQ_OFF;
    const uint32_t pbase = sb + PAIRS_OFF + (uint32_t)kq * PAIR_STRIDE;

    // PDL: wait for prep_kernel before touching its outputs
    cudaGridDependencySynchronize();

    // initial loads: Q (t<64) + this pair's tile 0 (keys kq*1024 + pt)
    if (t < 64)
        CP_ASYNC16(sbQ + (uint32_t)t * 16u, (const char*)(g_Qh + ((size_t)b * NN + q0 + t) * 8));
    {
        const size_t key0 = (size_t)b * NN + kq * 1024 + pt;
        CP_ASYNC16(pbase + (uint32_t)pt * 16u, (const char*)(g_Kh + key0 * 8));
#pragma unroll
        for (int c = 0; c < 8; c++)
            CP_ASYNC16(pbase + 2048u + swz128((uint32_t)pt * 128u + (uint32_t)c * 16u),
                       (const char*)(g_Vh + key0 * 64 + c * 8));
    }
    CP_COMMIT();

    uint32_t o[2][16];                          // [rowfrag][nt*2+d] f16x2 accumulators
#pragma unroll
    for (int rf = 0; rf < 2; rf++)
#pragma unroll
        for (int i = 0; i < 16; i++) o[rf][i] = 0u;
    float lacc[4] = {0.f, 0.f, 0.f, 0.f};       // row sums: [rf*2+d]
    uint32_t qa[4];

    CP_WAIT0();
    __syncthreads();        // Q visible to all; tile 0 visible within pair
    LDSM_X4(qa[0], qa[1], qa[2], qa[3], sbQ + (uint32_t)(rowgrp * 32 + lane) * 16u);

    for (int it = 0; it < 16; it++) {
        if (it + 1 < 16) {  // prefetch this pair's next 64-key tile
            const size_t keyn = (size_t)b * NN + kq * 1024 + (it + 1) * 64 + pt;
            const uint32_t nb = (uint32_t)((it + 1) & 1);
            CP_ASYNC16(pbase + nb * 1024u + (uint32_t)pt * 16u, (const char*)(g_Kh + keyn * 8));
#pragma unroll
            for (int c = 0; c < 8; c++)
                CP_ASYNC16(pbase + 2048u + nb * 8192u + swz128((uint32_t)pt * 128u + (uint32_t)c * 16u),
                           (const char*)(g_Vh + keyn * 64 + c * 8));
            CP_COMMIT();
        }

        const uint32_t kbuf = pbase + (uint32_t)(it & 1) * 1024u;
        const uint32_t vbuf = pbase + 2048u + (uint32_t)(it & 1) * 8192u;

#pragma unroll
        for (int half = 0; half < 2; half++) {
            uint32_t kb[4];     // 32 keys of this half
            LDSM_X4(kb[0], kb[1], kb[2], kb[3], kbuf + (uint32_t)(half * 32 + lane) * 16u);

            // ---- all 8 MMA1s up front (chunks A and B) ----
            uint32_t sA[8], sB[8];
            mma16808h(sA + 0, qa[0], qa[1], kb[0]);
            mma16808h(sA + 2, qa[0], qa[1], kb[1]);
            mma16808h(sA + 4, qa[2], qa[3], kb[0]);
            mma16808h(sA + 6, qa[2], qa[3], kb[1]);
            mma16808h(sB + 0, qa[0], qa[1], kb[2]);
            mma16808h(sB + 2, qa[0], qa[1], kb[3]);
            mma16808h(sB + 4, qa[2], qa[3], kb[2]);
            mma16808h(sB + 6, qa[2], qa[3], kb[3]);

            // ---- chunk A: EX2 (overlaps MMA1(B)) -> LDSM V -> MMA2 ----
            EX2H2(sA[0]); EX2H2(sA[1]); EX2H2(sA[2]); EX2H2(sA[3]);
            EX2H2(sA[4]); EX2H2(sA[5]); EX2H2(sA[6]); EX2H2(sA[7]);
            {
                uint32_t vb[16];
                const uint32_t vkey = (uint32_t)(half * 32 + ((lane >> 3) & 1) * 8 + (lane & 7));
#pragma unroll
                for (int ntp = 0; ntp < 4; ntp++) {
                    uint32_t cb = (uint32_t)(ntp * 2 + (lane >> 4));
                    LDSM_X4T(vb[4 * ntp], vb[4 * ntp + 1], vb[4 * ntp + 2], vb[4 * ntp + 3],
                             vbuf + swz128(vkey * 128u + cb * 16u));
                }
#pragma unroll
                for (int nt = 0; nt < 8; nt++) {
                    mma16816h(&o[0][2 * nt], sA + 0, vb[2 * nt], vb[2 * nt + 1]);
                    mma16816h(&o[1][2 * nt], sA + 4, vb[2 * nt], vb[2 * nt + 1]);
                }
            }

            // ---- chunk B: EX2 (overlaps MMA2(A)) -> LDSM V -> MMA2 ----
            EX2H2(sB[0]); EX2H2(sB[1]); EX2H2(sB[2]); EX2H2(sB[3]);
            EX2H2(sB[4]); EX2H2(sB[5]); EX2H2(sB[6]); EX2H2(sB[7]);
            {
                uint32_t vb[16];
                const uint32_t vkey = (uint32_t)(half * 32 + 16 + ((lane >> 3) & 1) * 8 + (lane & 7));
#pragma unroll
                for (int ntp = 0; ntp < 4; ntp++) {
                    uint32_t cb = (uint32_t)(ntp * 2 + (lane >> 4));
                    LDSM_X4T(vb[4 * ntp], vb[4 * ntp + 1], vb[4 * ntp + 2], vb[4 * ntp + 3],
                             vbuf + swz128(vkey * 128u + cb * 16u));
                }
#pragma unroll
                for (int nt = 0; nt < 8; nt++) {
                    mma16816h(&o[0][2 * nt], sB + 0, vb[2 * nt], vb[2 * nt + 1]);
                    mma16816h(&o[1][2 * nt], sB + 4, vb[2 * nt], vb[2 * nt + 1]);
                }
            }

            // ---- row sums (off critical path) ----
            lacc[0] += h2sumf(hadd2u(sA[0], sA[2])) + h2sumf(hadd2u(sB[0], sB[2]));
            lacc[1] += h2sumf(hadd2u(sA[1], sA[3])) + h2sumf(hadd2u(sB[1], sB[3]));
            lacc[2] += h2sumf(hadd2u(sA[4], sA[6])) + h2sumf(hadd2u(sB[4], sB[6]));
            lacc[3] += h2sumf(hadd2u(sA[5], sA[7])) + h2sumf(hadd2u(sB[5], sB[7]));
        }

        if (it + 1 < 16) {
            CP_WAIT0();          // this thread's prefetch landed
            PAIR_BAR(kq);        // 2-warp sync: next buffer full, old buffer free
        }
    }

    // ---- epilogue: combine 4 key-quarters through smem ----
#pragma unroll
    for (int j = 0; j < 4; j++) {
        lacc[j] += __shfl_xor_sync(0xffffffffu, lacc[j], 1);
        lacc[j] += __shfl_xor_sync(0xffffffffu, lacc[j], 2);
    }
    const float gma = __ldg(gamma_p);

    __syncthreads();            // ALL pairs done with their buffers -> reuse region

    __half* sOp = (__half*)(dynsm + PAIRS_OFF);             // [kq][ch 64][q 64] f16
    float*  sL  = (float*)(dynsm + PAIRS_OFF + 32768u);     // [kq][64] row sums

    if ((lane & 3) == 0) {
#pragma unroll
        for (int j = 0; j < 4; j++) {       // j = rf*2 + d -> row offset rf*16 + d*8
            int row = rowgrp * 32 + (j >> 1) * 16 + (j & 1) * 8 + (lane >> 2);
            sL[kq * 64 + row] = lacc[j];
        }
    }
#pragma unroll
    for (int rf = 0; rf < 2; rf++)
#pragma unroll
        for (int nt = 0; nt < 8; nt++)
#pragma unroll
            for (int d = 0; d < 2; d++) {
                __half2 hv = *reinterpret_cast<__half2*>(&o[rf][nt * 2 + d]);
                int row = rowgrp * 32 + rf * 16 + d * 8 + (lane >> 2);
                int c0  = nt * 8 + (lane & 3) * 2;
                sOp[(kq * 64 + c0) * 64 + row]       = __low2half(hv);
                sOp[(kq * 64 + c0 + 1) * 64 + row]   = __high2half(hv);
            }
    __syncthreads();

    // final: thread owns q = t&63, channels (t>>6) + 4*i
    {
        const int q = t & 63;
        const float l = sL[q] + sL[64 + q] + sL[128 + q] + sL[192 + q];
        const float inv = gma / l;
#pragma unroll
        for (int i = 0; i < 16; i++) {
            int c = (t >> 6) + 4 * i;
            float acc = (float)sOp[(0 * 64 + c) * 64 + q] + (float)sOp[(1 * 64 + c) * 64 + q]
                      + (float)sOp[(2 * 64 + c) * 64 + q] + (float)sOp[(3 * 64 + c) * 64 + q];
            size_t idx = ((size_t)b * 64 + c) * NN + q0 + q;
            out[idx] = acc * inv + x[idx];
        }
    }
}

// ---------------------------------------------------------------------------
extern "C" void kernel_launch(void* const* d_in, const int* in_sizes, int n_in,
                              void* d_out, int out_size) {
    (void)in_sizes; (void)n_in; (void)out_size;
    const float* x     = (const float*)d_in[0];
    const float* Wq    = (const float*)d_in[1];
    const float* bq    = (const float*)d_in[2];
    const float* Wk    = (const float*)d_in[3];
    const float* bk    = (const float*)d_in[4];
    const float* Wv    = (const float*)d_in[5];
    const float* bv    = (const float*)d_in[6];
    const float* gamma = (const float*)d_in[7];
    float* out = (float*)d_out;

    cudaFuncSetAttribute(attn_kernel, cudaFuncAttributeMaxDynamicSharedMemorySize,
                         (int)DSMEM_BYTES);

    prep_kernel<<<dim3(64, NB), 256>>>(x, Wq, bq, Wk, bk, Wv, bv);

    // attn with programmatic stream serialization
    cudaLaunchConfig_t cfg = {};
    cfg.gridDim  = dim3(64, NB);
    cfg.blockDim = dim3(256);
    cfg.dynamicSmemBytes = DSMEM_BYTES;
    cfg.stream = 0;
    cudaLaunchAttribute attrs[1];
    attrs[0].id = cudaLaunchAttributeProgrammaticStreamSerialization;
    attrs[0].val.programmaticStreamSerializationAllowed = 1;
    cfg.attrs = attrs;
    cfg.numAttrs = 1;
    cudaLaunchKernelEx(&cfg, attn_kernel, x, gamma, out);
}

// round 11
// speedup vs baseline: 1.3000x; 1.3000x over previous
#include <cuda_runtime.h>
#include <cuda_fp16.h>
#include <cstdint>

#define NB 4
#define NN 4096
#define LOG2E 1.4426950408889634f

// ---------------- scratch (__device__ globals; no allocation) ----------------
__device__ __align__(256) __half g_Qh[NB * NN * 8];   // [b][n][8], pre-scaled by log2e
__device__ __align__(256) __half g_Kh[NB * NN * 8];   // [b][n][8]
__device__ __align__(256) __half g_Vh[NB * NN * 64];  // [b][n][64]
__device__ unsigned g_bar[NB];                        // monotonic ticket barrier (replay-safe)

// ---------------- helpers ----------------
__device__ __forceinline__ uint32_t smem_u32(const void* p) {
    uint32_t a;
    asm("{ .reg .u64 t; cvta.to.shared.u64 t, %1; cvt.u32.u64 %0, t; }" : "=r"(a) : "l"(p));
    return a;
}
__device__ __forceinline__ uint32_t swz128(uint32_t b) { return b ^ ((b >> 3) & 0x70u); }

#define CP_ASYNC16(dst, src) \
    asm volatile("cp.async.cg.shared.global [%0], [%1], 16;" :: "r"(dst), "l"(src) : "memory")
#define CP_COMMIT() asm volatile("cp.async.commit_group;" ::: "memory")
#define CP_WAIT0()  asm volatile("cp.async.wait_group 0;" ::: "memory")
#define CP_WAIT1()  asm volatile("cp.async.wait_group 1;" ::: "memory")

#define LDSM_X4(r0, r1, r2, r3, a) \
    asm volatile("ldmatrix.sync.aligned.m8n8.x4.shared.b16 {%0,%1,%2,%3}, [%4];" \
                 : "=r"(r0), "=r"(r1), "=r"(r2), "=r"(r3) : "r"(a))
#define LDSM_X4T(r0, r1, r2, r3, a) \
    asm volatile("ldmatrix.sync.aligned.m8n8.x4.trans.shared.b16 {%0,%1,%2,%3}, [%4];" \
                 : "=r"(r0), "=r"(r1), "=r"(r2), "=r"(r3) : "r"(a))

// S(16x8,f16) = Q(16x8,f16) @ K^T ; C = 0
__device__ __forceinline__ void mma16808h(uint32_t* d, uint32_t a0, uint32_t a1, uint32_t b0) {
    uint32_t z = 0;
    asm volatile("mma.sync.aligned.m16n8k8.row.col.f16.f16.f16.f16 "
                 "{%0,%1}, {%2,%3}, {%4}, {%5,%5};"
                 : "=r"(d[0]), "=r"(d[1]) : "r"(a0), "r"(a1), "r"(b0), "r"(z));
}
// O(16x8,f16) += P(16x16,f16) @ V(16x8,f16)
__device__ __forceinline__ void mma16816h(uint32_t* d, const uint32_t* a, uint32_t b0, uint32_t b1) {
    asm volatile("mma.sync.aligned.m16n8k16.row.col.f16.f16.f16.f16 "
                 "{%0,%1}, {%2,%3,%4,%5}, {%6,%7}, {%0,%1};"
                 : "+r"(d[0]), "+r"(d[1])
                 : "r"(a[0]), "r"(a[1]), "r"(a[2]), "r"(a[3]), "r"(b0), "r"(b1));
}
#define EX2H2(r) asm volatile("ex2.approx.f16x2 %0, %0;" : "+r"(r))
__device__ __forceinline__ uint32_t hadd2u(uint32_t a, uint32_t b) {
    uint32_t d; asm("add.rn.f16x2 %0, %1, %2;" : "=r"(d) : "r"(a), "r"(b)); return d;
}
__device__ __forceinline__ float h2sumf(uint32_t r) {
    __half2 h = *reinterpret_cast<__half2*>(&r);
    return __low2float(h) + __high2float(h);
}

// ---------------- smem layout (dynamic, 56320 B) ----------------
// Phase P (prep): XS f32[64*64] @0 (16KB) | WS f32[80*64] @16384 (20KB,
//   staging reuse) | BS f32[80] @36864
// Phase A (attn): sQ @0 (1KB) | 3 stages @1024, stride 18432 (K 2KB + V 16KB)
//   epilogue: sOp @1024 (32KB) | sL @33792 (1KB)
#define SM_XS 0u
#define SM_WS 16384u
#define SM_BS 36864u
#define SM_SQ 0u
#define SM_ST 1024u
#define STAGE 18432u
#define SM_OP 1024u
#define SM_L  33792u
#define DSMEM_BYTES 56320u

__global__ __launch_bounds__(256, 2) void fused_kernel(
    const float* __restrict__ x,
    const float* __restrict__ Wq, const float* __restrict__ bq,
    const float* __restrict__ Wk, const float* __restrict__ bk,
    const float* __restrict__ Wv, const float* __restrict__ bv,
    const float* __restrict__ gamma_p,
    float* __restrict__ out)
{
    extern __shared__ __align__(1024) unsigned char dynsm[];

    const int t    = threadIdx.x;
    const int lane = t & 31;
    const int w    = t >> 5;
    const int b    = blockIdx.y;
    const int n0   = blockIdx.x * 64;    // == q0 in attn phase

    // ======================= Phase P: QKV projections =======================
    {
        float* xs = (float*)(dynsm + SM_XS);
        float* ws = (float*)(dynsm + SM_WS);
        float* bs = (float*)(dynsm + SM_BS);

        for (int lin = t; lin < 80 * 64; lin += 256) {
            int o = lin >> 6, c = lin & 63;
            float wv;
            if (o < 8)       wv = Wq[o * 64 + c] * LOG2E;
            else if (o < 16) wv = Wk[(o - 8) * 64 + c];
            else             wv = Wv[(o - 16) * 64 + c];
            ws[o * 64 + c] = wv;
        }
        if (t < 80) {
            float bb;
            if (t < 8)       bb = bq[t] * LOG2E;
            else if (t < 16) bb = bk[t - 8];
            else             bb = bv[t - 16];
            bs[t] = bb;
        }
        for (int lin = t; lin < 64 * 64; lin += 256) {
            int c = lin >> 6, i = lin & 63;
            xs[c * 64 + i] = x[(b * 64 + c) * NN + n0 + i];
        }
        __syncthreads();

        const int tx = t & 63;
        const int ty = t >> 6;

        float acc[20];
#pragma unroll
        for (int i = 0; i < 20; i++) acc[i] = 0.f;
#pragma unroll
        for (int c = 0; c < 64; c++) {
            float xv = xs[c * 64 + tx];
#pragma unroll
            for (int oo = 0; oo < 20; oo++)
                acc[oo] += ws[(ty * 20 + oo) * 64 + c] * xv;
        }
        float bias[20];
#pragma unroll
        for (int oo = 0; oo < 20; oo++) bias[oo] = bs[ty * 20 + oo];

        __syncthreads();   // done reading ws -> reuse as staging

        // staging: SQ [pix][8ch] (1024B) | SK same | SV [pix][64ch], 136B rows
        char* stage = (char*)ws;
#pragma unroll
        for (int oo = 0; oo < 20; oo++) {
            int o = ty * 20 + oo;
            __half h = __float2half(acc[oo] + bias[oo]);
            if (o < 8)
                *(__half*)(stage + tx * 16 + o * 2) = h;
            else if (o < 16)
                *(__half*)(stage + 1024 + tx * 16 + (o - 8) * 2) = h;
            else
                *(__half*)(stage + 2048 + tx * 136 + (o - 16) * 2) = h;
        }
        __syncthreads();

        if (t < 64) {
            *(uint4*)(g_Qh + ((size_t)b * NN + n0 + t) * 8) = *(const uint4*)(stage + t * 16);
        } else if (t < 128) {
            int i = t - 64;
            *(uint4*)(g_Kh + ((size_t)b * NN + n0 + i) * 8) = *(const uint4*)(stage + 1024 + i * 16);
        }
#pragma unroll
        for (int i = 0; i < 4; i++) {
            int lin = t + i * 256;               // 1024 chunks of 8B
            int pix = lin >> 4, chk = lin & 15;
            *(uint2*)(g_Vh + ((size_t)b * NN + n0 + pix) * 64 + chk * 4) =
                *(const uint2*)(stage + 2048 + pix * 136 + chk * 8);
        }
    }

    // ============== per-batch grid barrier (64 CTAs, replay-safe) ==============
    __threadfence();
    __syncthreads();
    if (t == 0) {
        unsigned ticket = atomicAdd(&g_bar[b], 1u);
        unsigned target = (ticket / 64u + 1u) * 64u;
        while (atomicAdd(&g_bar[b], 0u) < target) { }
        __threadfence();
    }
    __syncthreads();   // releases all threads; also guards smem reuse below

    // ======================= Phase A: flash attention =======================
    const int rowgrp = w >> 2;          // 0,1 -> rows [32*rowgrp, +32)
    const int kq     = w & 3;           // key quarter within each 128-key tile
    const uint32_t sb  = smem_u32(dynsm);
    const uint32_t sbQ = sb + SM_SQ;

    // prologue: Q + tile0 (group 0), tile1 (group 1)
    if (t < 64)
        CP_ASYNC16(sbQ + (uint32_t)t * 16u, (const char*)(g_Qh + ((size_t)b * NN + n0 + t) * 8));
    {
        const uint32_t st0 = sb + SM_ST;
        if (t < 128)
            CP_ASYNC16(st0 + (uint32_t)t * 16u, (const char*)(g_Kh + ((size_t)b * NN + t) * 8));
#pragma unroll
        for (int i = 0; i < 4; i++) {
            int cid = t + i * 256;
            int vk = cid >> 3, vc = cid & 7;
            CP_ASYNC16(st0 + 2048u + swz128((uint32_t)vk * 128u + (uint32_t)vc * 16u),
                       (const char*)(g_Vh + ((size_t)b * NN + vk) * 64 + vc * 8));
        }
    }
    CP_COMMIT();
    {
        const uint32_t st1 = sb + SM_ST + STAGE;
        if (t < 128)
            CP_ASYNC16(st1 + (uint32_t)t * 16u, (const char*)(g_Kh + ((size_t)b * NN + 128 + t) * 8));
#pragma unroll
        for (int i = 0; i < 4; i++) {
            int cid = t + i * 256;
            int vk = cid >> 3, vc = cid & 7;
            CP_ASYNC16(st1 + 2048u + swz128((uint32_t)vk * 128u + (uint32_t)vc * 16u),
                       (const char*)(g_Vh + ((size_t)b * NN + 128 + vk) * 64 + vc * 8));
        }
    }
    CP_COMMIT();

    uint32_t o[2][16];
#pragma unroll
    for (int rf = 0; rf < 2; rf++)
#pragma unroll
        for (int i = 0; i < 16; i++) o[rf][i] = 0u;
    float lacc[4] = {0.f, 0.f, 0.f, 0.f};
    uint32_t qa[4];

    for (int it = 0; it < 32; it++) {
        if (it == 31) { CP_WAIT0(); } else { CP_WAIT1(); }   // tile `it` landed
        __syncthreads();   // all warps done with tile it-1 -> its buffer reusable

        if (it + 2 < 32) {  // prefetch tile it+2 into stage (it+2)%3
            const uint32_t std = sb + SM_ST + (uint32_t)((it + 2) % 3) * STAGE;
            const int kbase = (it + 2) * 128;
            if (t < 128)
                CP_ASYNC16(std + (uint32_t)t * 16u,
                           (const char*)(g_Kh + ((size_t)b * NN + kbase + t) * 8));
#pragma unroll
            for (int i = 0; i < 4; i++) {
                int cid = t + i * 256;
                int vk = cid >> 3, vc = cid & 7;
                CP_ASYNC16(std + 2048u + swz128((uint32_t)vk * 128u + (uint32_t)vc * 16u),
                           (const char*)(g_Vh + ((size_t)b * NN + kbase + vk) * 64 + vc * 8));
            }
            CP_COMMIT();
        }

        if (it == 0) {  // Q A-frags, resident all loop
            LDSM_X4(qa[0], qa[1], qa[2], qa[3], sbQ + (uint32_t)(rowgrp * 32 + lane) * 16u);
        }

        const uint32_t kbuf = sb + SM_ST + (uint32_t)(it % 3) * STAGE;
        const uint32_t vbuf = kbuf + 2048u;

        uint32_t kb[4];     // this warp's 32-key quarter
        LDSM_X4(kb[0], kb[1], kb[2], kb[3], kbuf + (uint32_t)(kq * 32 + lane) * 16u);

        // ---- all 8 MMA1s up front ----
        uint32_t sA[8], sB[8];
        mma16808h(sA + 0, qa[0], qa[1], kb[0]);
        mma16808h(sA + 2, qa[0], qa[1], kb[1]);
        mma16808h(sA + 4, qa[2], qa[3], kb[0]);
        mma16808h(sA + 6, qa[2], qa[3], kb[1]);
        mma16808h(sB + 0, qa[0], qa[1], kb[2]);
        mma16808h(sB + 2, qa[0], qa[1], kb[3]);
        mma16808h(sB + 4, qa[2], qa[3], kb[2]);
        mma16808h(sB + 6, qa[2], qa[3], kb[3]);

        // ---- chunk A: EX2 (overlaps MMA1(B)) -> LDSM V -> MMA2 ----
        EX2H2(sA[0]); EX2H2(sA[1]); EX2H2(sA[2]); EX2H2(sA[3]);
        EX2H2(sA[4]); EX2H2(sA[5]); EX2H2(sA[6]); EX2H2(sA[7]);
        {
            uint32_t vb[16];
            const uint32_t vkey = (uint32_t)(kq * 32 + ((lane >> 3) & 1) * 8 + (lane & 7));
#pragma unroll
            for (int ntp = 0; ntp < 4; ntp++) {
                uint32_t cb = (uint32_t)(ntp * 2 + (lane >> 4));
                LDSM_X4T(vb[4 * ntp], vb[4 * ntp + 1], vb[4 * ntp + 2], vb[4 * ntp + 3],
                         vbuf + swz128(vkey * 128u + cb * 16u));
            }
#pragma unroll
            for (int nt = 0; nt < 8; nt++) {
                mma16816h(&o[0][2 * nt], sA + 0, vb[2 * nt], vb[2 * nt + 1]);
                mma16816h(&o[1][2 * nt], sA + 4, vb[2 * nt], vb[2 * nt + 1]);
            }
        }

        // ---- chunk B: EX2 (overlaps MMA2(A)) -> LDSM V -> MMA2 ----
        EX2H2(sB[0]); EX2H2(sB[1]); EX2H2(sB[2]); EX2H2(sB[3]);
        EX2H2(sB[4]); EX2H2(sB[5]); EX2H2(sB[6]); EX2H2(sB[7]);
        {
            uint32_t vb[16];
            const uint32_t vkey = (uint32_t)(kq * 32 + 16 + ((lane >> 3) & 1) * 8 + (lane & 7));
#pragma unroll
            for (int ntp = 0; ntp < 4; ntp++) {
                uint32_t cb = (uint32_t)(ntp * 2 + (lane >> 4));
                LDSM_X4T(vb[4 * ntp], vb[4 * ntp + 1], vb[4 * ntp + 2], vb[4 * ntp + 3],
                         vbuf + swz128(vkey * 128u + cb * 16u));
            }
#pragma unroll
            for (int nt = 0; nt < 8; nt++) {
                mma16816h(&o[0][2 * nt], sB + 0, vb[2 * nt], vb[2 * nt + 1]);
                mma16816h(&o[1][2 * nt], sB + 4, vb[2 * nt], vb[2 * nt + 1]);
            }
        }

        // ---- row sums (off critical path) ----
        lacc[0] += h2sumf(hadd2u(sA[0], sA[2])) + h2sumf(hadd2u(sB[0], sB[2]));
        lacc[1] += h2sumf(hadd2u(sA[1], sA[3])) + h2sumf(hadd2u(sB[1], sB[3]));
        lacc[2] += h2sumf(hadd2u(sA[4], sA[6])) + h2sumf(hadd2u(sB[4], sB[6]));
        lacc[3] += h2sumf(hadd2u(sA[5], sA[7])) + h2sumf(hadd2u(sB[5], sB[7]));
    }

    // ---- epilogue: combine 4 key-quarters through smem ----
#pragma unroll
    for (int j = 0; j < 4; j++) {
        lacc[j] += __shfl_xor_sync(0xffffffffu, lacc[j], 1);
        lacc[j] += __shfl_xor_sync(0xffffffffu, lacc[j], 2);
    }
    const float gma = __ldg(gamma_p);

    __syncthreads();            // all loop reads of stages done -> reuse region

    __half* sOp = (__half*)(dynsm + SM_OP);     // [kq][ch 64][q 64] f16 partials
    float*  sL  = (float*)(dynsm + SM_L);       // [kq][64] partial row sums

    if ((lane & 3) == 0) {
#pragma unroll
        for (int j = 0; j < 4; j++) {           // j = rf*2+d -> row rf*16 + d*8
            int row = rowgrp * 32 + (j >> 1) * 16 + (j & 1) * 8 + (lane >> 2);
            sL[kq * 64 + row] = lacc[j];
        }
    }
#pragma unroll
    for (int rf = 0; rf < 2; rf++)
#pragma unroll
        for (int nt = 0; nt < 8; nt++)
#pragma unroll
            for (int d = 0; d < 2; d++) {
                __half2 hv = *reinterpret_cast<__half2*>(&o[rf][nt * 2 + d]);
                int row = rowgrp * 32 + rf * 16 + d * 8 + (lane >> 2);
                int c0  = nt * 8 + (lane & 3) * 2;
                sOp[(kq * 64 + c0) * 64 + row]     = __low2half(hv);
                sOp[(kq * 64 + c0 + 1) * 64 + row] = __high2half(hv);
            }
    __syncthreads();

    // final: thread owns q = t&63, channels (t>>6) + 4*i
    {
        const int q = t & 63;
        const float l = sL[q] + sL[64 + q] + sL[128 + q] + sL[192 + q];
        const float inv = gma / l;
#pragma unroll
        for (int i = 0; i < 16; i++) {
            int c = (t >> 6) + 4 * i;
            float acc = (float)sOp[(0 * 64 + c) * 64 + q] + (float)sOp[(1 * 64 + c) * 64 + q]
                      + (float)sOp[(2 * 64 + c) * 64 + q] + (float)sOp[(3 * 64 + c) * 64 + q];
            size_t idx = ((size_t)b * 64 + c) * NN + n0 + q;
            out[idx] = acc * inv + x[idx];
        }
    }
}

// ---------------------------------------------------------------------------
extern "C" void kernel_launch(void* const* d_in, const int* in_sizes, int n_in,
                              void* d_out, int out_size) {
    (void)in_sizes; (void)n_in; (void)out_size;
    const float* x     = (const float*)d_in[0];
    const float* Wq    = (const float*)d_in[1];
    const float* bq    = (const float*)d_in[2];
    const float* Wk    = (const float*)d_in[3];
    const float* bk    = (const float*)d_in[4];
    const float* Wv    = (const float*)d_in[5];
    const float* bv    = (const float*)d_in[6];
    const float* gamma = (const float*)d_in[7];
    float* out = (float*)d_out;

    cudaFuncSetAttribute(fused_kernel, cudaFuncAttributeMaxDynamicSharedMemorySize,
                         (int)DSMEM_BYTES);
    fused_kernel<<<dim3(64, NB), 256, DSMEM_BYTES>>>(
        x, Wq, bq, Wk, bk, Wv, bv, gamma, out);
}